// round 14
// baseline (speedup 1.0000x reference)
#include <cuda_runtime.h>
#include <math.h>

// CTC loss forward. 64 CTAs x 128 threads (4 warps, 1/SMSP). Two positions
// per thread in f32x2, block-floating-point alpha (linear float2 mantissa +
// int exponent), EIGHT time steps fused per __syncthreads, zero MUFU in the
// loop. Window = 9 pairs (18 positions); 8-layer in-place packed pyramid
// (8+7+6+5+4+3+2+1 updates, descending-k in-place).
// B=64, T=1000, C=128 (blank=127), L=100, S=201.

#define Bc 64
#define Tc 1000
#define Cc 128
#define Lc 100
#define NTHREADS 128
#define NPAIR 128
#define PADP 8
#define EDEAD (-(1 << 29))

#define EPSV (1e-7f)
#define LN2F 0.6931471805599453f

__device__ __forceinline__ float lg2a(float x) {
    float y; asm("lg2.approx.f32 %0, %1;" : "=f"(y) : "f"(x)); return y;
}
__device__ __forceinline__ float2 add2(float2 a, float2 b) {
    float2 r;
    asm("{\n\t.reg .b64 A,B,D;\n\t"
        "mov.b64 A,{%2,%3};\n\tmov.b64 B,{%4,%5};\n\t"
        "add.rn.f32x2 D,A,B;\n\t"
        "mov.b64 {%0,%1},D;\n\t}"
        : "=f"(r.x), "=f"(r.y)
        : "f"(a.x), "f"(a.y), "f"(b.x), "f"(b.y));
    return r;
}
__device__ __forceinline__ float2 mul2(float2 a, float2 b) {
    float2 r;
    asm("{\n\t.reg .b64 A,B,D;\n\t"
        "mov.b64 A,{%2,%3};\n\tmov.b64 B,{%4,%5};\n\t"
        "mul.rn.f32x2 D,A,B;\n\t"
        "mov.b64 {%0,%1},D;\n\t}"
        : "=f"(r.x), "=f"(r.y)
        : "f"(a.x), "f"(a.y), "f"(b.x), "f"(b.y));
    return r;
}
__device__ __forceinline__ float2 fma2(float2 a, float2 b, float2 c) {
    float2 r;
    asm("{\n\t.reg .b64 A,B,C,D;\n\t"
        "mov.b64 A,{%2,%3};\n\tmov.b64 B,{%4,%5};\n\tmov.b64 C,{%6,%7};\n\t"
        "fma.rn.f32x2 D,A,B,C;\n\t"
        "mov.b64 {%0,%1},D;\n\t}"
        : "=f"(r.x), "=f"(r.y)
        : "f"(a.x), "f"(a.y), "f"(b.x), "f"(b.y), "f"(c.x), "f"(c.y));
    return r;
}
// Exact 2^d (d int), clamped to 0 below representable range.
__device__ __forceinline__ float exp2i(int d) {
    int e = 127 + d; e = e < 0 ? 0 : e;
    return __int_as_float(e << 23);
}
// One CTC step for pair j: lo = (v2j + v2j-1)*pb; hi = (v2j+1 + v2j + sk*v2j-1)*po
__device__ __forceinline__ float2 upd(float2 Q, float2 Qm1, float2 SK, float2 P) {
    float2 S1 = make_float2(Qm1.y, Q.x);
    return mul2(fma2(SK, Qm1, add2(Q, S1)), P);
}

// Flat offsets for the triangular prob array: layer L holds 8-L values.
__device__ __constant__ const int OFFT[8] = {0, 8, 15, 21, 26, 30, 33, 35};

__global__ __launch_bounds__(NTHREADS, 1)
void ctc_loss_kernel(const int* __restrict__ y_true,
                     const float* __restrict__ y_pred,
                     const int* __restrict__ input_len,
                     const int* __restrict__ label_len,
                     float* __restrict__ out)
{
    const int b = blockIdx.x;
    const int i = threadIdx.x;                 // pair index

    __shared__ float2 mbuf[2][PADP + NPAIR];
    __shared__ int    ebuf[2][PADP + NPAIR];
    __shared__ int    labels[Lc];

    if (i < Lc) labels[i] = y_true[b * Lc + i];
    if (i < PADP) {
        mbuf[0][i] = make_float2(0.f, 0.f);
        mbuf[1][i] = make_float2(0.f, 0.f);
        ebuf[0][i] = EDEAD;
        ebuf[1][i] = EDEAD;
    }
    __syncthreads();

    // Static per-thread info for pairs i-7..i (odd-position class + skip).
    int    oc[8];
    float2 SK[8];
    #pragma unroll
    for (int k = 0; k < 8; ++k) {
        int pj = i - 7 + k;
        int cj = pj < 0 ? 0 : (pj > Lc - 1 ? Lc - 1 : pj);
        oc[k] = labels[cj];
        int cjm = cj > 0 ? cj - 1 : 0;
        float sk = (pj >= 1 && labels[cj] != labels[cjm]) ? 1.f : 0.f;
        SK[k] = make_float2(0.f, sk);
    }

    int Tb = input_len[b]; if (Tb > Tc) Tb = Tc;
    const int smax = 2 * label_len[b];
    const float* base = y_pred + (size_t)b * Tc * Cc;

    // BFP init: pair 0 alive with E=0, others dead.
    float2 A = make_float2(0.f, 0.f);
    int    E = EDEAD;
    if (i == 0) {
        A = make_float2(base[Cc - 1] + EPSV, base[oc[7]] + EPSV);
        E = 0;
    }

    // Prefetch prob scalars for the first iteration (rows 1..8; Tb >= 500).
    float pnv[36], pnb[8];
    {
        int idx = 0;
        #pragma unroll
        for (int L = 0; L < 8; ++L) {
            const float* R = base + (size_t)(1 + L) * Cc;
            pnb[L] = R[Cc - 1];
            #pragma unroll
            for (int k = L; k < 8; ++k) pnv[idx++] = R[oc[k]];
        }
    }

    int it = 0;
    int t = 1;

    for (; t + 7 < Tb; t += 8, ++it) {
        // Consume prefetched probs (+eps) into this iteration's registers.
        float pcv[36], pcb[8];
        #pragma unroll
        for (int j = 0; j < 36; ++j) pcv[j] = pnv[j] + EPSV;
        #pragma unroll
        for (int j = 0; j < 8; ++j)  pcb[j] = pnb[j] + EPSV;

        float2* mb = mbuf[it & 1];
        int*    eb = ebuf[it & 1];
        mb[PADP + i] = A;
        eb[PADP + i] = E;
        __syncthreads();

        // Prefetch next iteration's probs (row base clamped in-bounds).
        {
            int r0 = t + 8; if (r0 > Tb - 8) r0 = Tb - 8;
            int idx = 0;
            #pragma unroll
            for (int L = 0; L < 8; ++L) {
                const float* R = base + (size_t)(r0 + L) * Cc;
                pnb[L] = R[Cc - 1];
                #pragma unroll
                for (int k = L; k < 8; ++k) pnv[idx++] = R[oc[k]];
            }
        }

        // Window: pairs i-8..i-1 from shared (+ exponents), own in registers.
        float2 W[8]; int Ew[8];
        #pragma unroll
        for (int j = 0; j < 8; ++j) { W[j] = mb[i + j]; Ew[j] = eb[i + j]; }

        // Align to max exponent (exact powers of two).
        int Em = E;
        #pragma unroll
        for (int j = 0; j < 8; ++j) Em = Ew[j] > Em ? Ew[j] : Em;

        float2 val[9];
        #pragma unroll
        for (int j = 0; j < 8; ++j) {
            float f = exp2i(Ew[j] - Em);
            val[j] = mul2(W[j], make_float2(f, f));
        }
        {
            float f = exp2i(E - Em);
            val[8] = mul2(A, make_float2(f, f));
        }

        // 8-layer in-place pyramid. Layer L updates pairs i-7+k, k = L..7
        // (val index k+1), descending k so in-place reads are pre-update.
        #pragma unroll
        for (int L = 0; L < 8; ++L) {
            float blv = pcb[L];
            #pragma unroll
            for (int k = 7; k >= L; --k) {
                float2 P = make_float2(blv, pcv[OFFT[L] + k - L]);
                val[k + 1] = upd(val[k + 1], val[k], SK[k], P);
            }
        }
        A = val[8];

        // Renormalize by exact 2^-e (e = exponent of the pair max).
        float m = fmaxf(A.x, A.y);
        int e = ((__float_as_int(m) >> 23) & 255) - 127;
        float sfac = exp2i(-e);
        A = mul2(A, make_float2(sfac, sfac));
        E = Em + e;
    }

    // Tail: 0..7 single steps (same BFP protocol, 1-pair window).
    for (; t < Tb; ++t, ++it) {
        float2* mb = mbuf[it & 1];
        int*    eb = ebuf[it & 1];
        mb[PADP + i] = A;
        eb[PADP + i] = E;
        __syncthreads();
        float2 N = mb[PADP + i - 1];
        int   En = eb[PADP + i - 1];
        int   Em = E > En ? E : En;
        float fo = exp2i(E - Em), fn = exp2i(En - Em);
        float2 Vo = mul2(A, make_float2(fo, fo));
        float2 Vn = mul2(N, make_float2(fn, fn));
        float pbv = base[(size_t)t * Cc + (Cc - 1)] + EPSV;
        float pov = base[(size_t)t * Cc + oc[7]]    + EPSV;
        A = upd(Vo, Vn, SK[7], make_float2(pbv, pov));
        float m = fmaxf(A.x, A.y);
        int e = ((__float_as_int(m) >> 23) & 255) - 127;
        float sfac = exp2i(-e);
        A = mul2(A, make_float2(sfac, sfac));
        E = Em + e;
    }

    // Final readout: positions smax (pair smax/2, lo) and smax-1
    // (pair smax/2-1, hi). smax is even and >= 100.
    float2* mb = mbuf[it & 1];
    int*    eb = ebuf[it & 1];
    mb[PADP + i] = A;
    eb[PADP + i] = E;
    __syncthreads();
    if (i == 0) {
        int   jL = smax >> 1;
        float mL = mb[PADP + jL].x;     int EL = eb[PADP + jL];
        float mP = mb[PADP + jL - 1].y; int EP = eb[PADP + jL - 1];
        int Em = EL > EP ? EL : EP;
        float r = mL * exp2i(EL - Em) + mP * exp2i(EP - Em);
        out[b] = -LN2F * (lg2a(r) + (float)Em);
    }
}

extern "C" void kernel_launch(void* const* d_in, const int* in_sizes, int n_in,
                              void* d_out, int out_size)
{
    const int*   y_true    = (const int*)  d_in[0];  // [B,L] int32
    const float* y_pred    = (const float*)d_in[1];  // [B,T,C] float32
    const int*   input_len = (const int*)  d_in[2];  // [B] int32
    const int*   label_len = (const int*)  d_in[3];  // [B] int32
    float*       out       = (float*)d_out;          // [B,1] float32

    ctc_loss_kernel<<<Bc, NTHREADS>>>(y_true, y_pred, input_len, label_len, out);
}

// round 16
// speedup vs baseline: 1.3525x; 1.3525x over previous
#include <cuda_runtime.h>
#include <math.h>

// CTC loss forward. 64 CTAs x 128 threads (4 warps, 1/SMSP). Two positions
// per thread in f32x2, block-floating-point alpha (linear float2 mantissa +
// int exponent), 4-step fused pyramid, zero MUFU in the loop.
// R15 = R11 with a DEPTH-2 probability prefetch pipeline: two 13-scalar
// buffers consumed alternately, each refilled for rows t+8 (=2 iterations
// ahead) right after the barrier. Arithmetic identical to R11.
// B=64, T=1000, C=128 (blank=127), L=100, S=201.

#define Bc 64
#define Tc 1000
#define Cc 128
#define Lc 100
#define NTHREADS 128
#define NPAIR 128
#define PADP 4
#define EDEAD (-(1 << 29))

#define EPSV (1e-7f)
#define LN2F 0.6931471805599453f

__device__ __forceinline__ float lg2a(float x) {
    float y; asm("lg2.approx.f32 %0, %1;" : "=f"(y) : "f"(x)); return y;
}
__device__ __forceinline__ float2 add2(float2 a, float2 b) {
    float2 r;
    asm("{\n\t.reg .b64 A,B,D;\n\t"
        "mov.b64 A,{%2,%3};\n\tmov.b64 B,{%4,%5};\n\t"
        "add.rn.f32x2 D,A,B;\n\t"
        "mov.b64 {%0,%1},D;\n\t}"
        : "=f"(r.x), "=f"(r.y)
        : "f"(a.x), "f"(a.y), "f"(b.x), "f"(b.y));
    return r;
}
__device__ __forceinline__ float2 mul2(float2 a, float2 b) {
    float2 r;
    asm("{\n\t.reg .b64 A,B,D;\n\t"
        "mov.b64 A,{%2,%3};\n\tmov.b64 B,{%4,%5};\n\t"
        "mul.rn.f32x2 D,A,B;\n\t"
        "mov.b64 {%0,%1},D;\n\t}"
        : "=f"(r.x), "=f"(r.y)
        : "f"(a.x), "f"(a.y), "f"(b.x), "f"(b.y));
    return r;
}
__device__ __forceinline__ float2 fma2(float2 a, float2 b, float2 c) {
    float2 r;
    asm("{\n\t.reg .b64 A,B,C,D;\n\t"
        "mov.b64 A,{%2,%3};\n\tmov.b64 B,{%4,%5};\n\tmov.b64 C,{%6,%7};\n\t"
        "fma.rn.f32x2 D,A,B,C;\n\t"
        "mov.b64 {%0,%1},D;\n\t}"
        : "=f"(r.x), "=f"(r.y)
        : "f"(a.x), "f"(a.y), "f"(b.x), "f"(b.y), "f"(c.x), "f"(c.y));
    return r;
}
// Exact 2^d (d int), clamped to 0 below representable range.
__device__ __forceinline__ float exp2i(int d) {
    int e = 127 + d; e = e < 0 ? 0 : e;
    return __int_as_float(e << 23);
}
// One CTC step for pair j: lo = (v2j + v2j-1)*pb; hi = (v2j+1 + v2j + sk*v2j-1)*po
__device__ __forceinline__ float2 upd(float2 Q, float2 Qm1, float2 SK, float2 P) {
    float2 S1 = make_float2(Qm1.y, Q.x);
    return mul2(fma2(SK, Qm1, add2(Q, S1)), P);
}

// 13-scalar probability set for one 4-step chunk (rows R..R+3).
struct PS {
    float bl[4];           // blank prob, rows R..R+3
    float o0;              // pair i-3 label col, row R
    float o1[2];           // pair i-2, rows R..R+1
    float o2[3];           // pair i-1, rows R..R+2
    float o3[4];           // pair i,   rows R..R+3
};

__device__ __forceinline__ void loadPS(PS& P, const float* R, const int* oc) {
    P.bl[0] = R[Cc - 1];          P.bl[1] = R[Cc + Cc - 1];
    P.bl[2] = R[2 * Cc + Cc - 1]; P.bl[3] = R[3 * Cc + Cc - 1];
    P.o0    = R[oc[0]];
    P.o1[0] = R[oc[1]];      P.o1[1] = R[Cc + oc[1]];
    P.o2[0] = R[oc[2]];      P.o2[1] = R[Cc + oc[2]]; P.o2[2] = R[2 * Cc + oc[2]];
    P.o3[0] = R[oc[3]];      P.o3[1] = R[Cc + oc[3]];
    P.o3[2] = R[2 * Cc + oc[3]]; P.o3[3] = R[3 * Cc + oc[3]];
}

// One fused 4-step iteration (identical arithmetic to R11). Consumes P,
// then refills P for rows tpre..tpre+3 (prefetch distance 2 iterations).
__device__ __forceinline__ void iter4(
    float2& A, int& E, PS& P, int tpre, int itp,
    const float* base, int Tb, const int* oc, const float2* SK,
    float2 (*mbuf)[PADP + NPAIR], int (*ebuf)[PADP + NPAIR], int i)
{
    // Pack current probabilities (+eps).
    float b0 = P.bl[0] + EPSV, b1 = P.bl[1] + EPSV;
    float b2 = P.bl[2] + EPSV, b3 = P.bl[3] + EPSV;
    float2 P1[4] = { make_float2(b0, P.o0    + EPSV),
                     make_float2(b0, P.o1[0] + EPSV),
                     make_float2(b0, P.o2[0] + EPSV),
                     make_float2(b0, P.o3[0] + EPSV) };
    float2 P2[3] = { make_float2(b1, P.o1[1] + EPSV),
                     make_float2(b1, P.o2[1] + EPSV),
                     make_float2(b1, P.o3[1] + EPSV) };
    float2 P3[2] = { make_float2(b2, P.o2[2] + EPSV),
                     make_float2(b2, P.o3[2] + EPSV) };
    float2 P4    =   make_float2(b3, P.o3[3] + EPSV);

    float2* mb = mbuf[itp];
    int*    eb = ebuf[itp];
    mb[PADP + i] = A;
    eb[PADP + i] = E;
    __syncthreads();

    // Refill P for rows tpre..tpre+3 (consumed 2 iterations from now).
    {
        int r0 = tpre; if (r0 > Tb - 4) r0 = Tb - 4;
        loadPS(P, base + (size_t)r0 * Cc, oc);
    }

    // Window: pairs i-4..i-1 from shared (+ exponents), own in registers.
    float2 W[4]; int Ew[4];
    #pragma unroll
    for (int j = 0; j < 4; ++j) { W[j] = mb[i + j]; Ew[j] = eb[i + j]; }

    // Align to max exponent (exact powers of two).
    int Em = E;
    #pragma unroll
    for (int j = 0; j < 4; ++j) Em = Ew[j] > Em ? Ew[j] : Em;

    float2 V[5];
    #pragma unroll
    for (int j = 0; j < 4; ++j) {
        float f = exp2i(Ew[j] - Em);
        V[j] = mul2(W[j], make_float2(f, f));
    }
    {
        float f = exp2i(E - Em);
        V[4] = mul2(A, make_float2(f, f));
    }

    // 4-layer packed pyramid.
    float2 L1[4];
    #pragma unroll
    for (int k = 0; k < 4; ++k) L1[k] = upd(V[k + 1], V[k], SK[k], P1[k]);
    float2 L2[3];
    #pragma unroll
    for (int k = 0; k < 3; ++k) L2[k] = upd(L1[k + 1], L1[k], SK[k + 1], P2[k]);
    float2 L3[2];
    #pragma unroll
    for (int k = 0; k < 2; ++k) L3[k] = upd(L2[k + 1], L2[k], SK[k + 2], P3[k]);
    A = upd(L3[1], L3[0], SK[3], P4);

    // Renormalize by exact 2^-e (e = exponent of the pair max).
    float m = fmaxf(A.x, A.y);
    int e = ((__float_as_int(m) >> 23) & 255) - 127;
    float sfac = exp2i(-e);
    A = mul2(A, make_float2(sfac, sfac));
    E = Em + e;
}

__global__ __launch_bounds__(NTHREADS, 1)
void ctc_loss_kernel(const int* __restrict__ y_true,
                     const float* __restrict__ y_pred,
                     const int* __restrict__ input_len,
                     const int* __restrict__ label_len,
                     float* __restrict__ out)
{
    const int b = blockIdx.x;
    const int i = threadIdx.x;                 // pair index

    __shared__ float2 mbuf[2][PADP + NPAIR];
    __shared__ int    ebuf[2][PADP + NPAIR];
    __shared__ int    labels[Lc];

    if (i < Lc) labels[i] = y_true[b * Lc + i];
    if (i < PADP) {
        mbuf[0][i] = make_float2(0.f, 0.f);
        mbuf[1][i] = make_float2(0.f, 0.f);
        ebuf[0][i] = EDEAD;
        ebuf[1][i] = EDEAD;
    }
    __syncthreads();

    // Static per-thread info for pairs i-3..i (odd-position class + skip).
    int    oc[4];
    float2 SK[4];
    #pragma unroll
    for (int k = 0; k < 4; ++k) {
        int pj = i - 3 + k;
        int cj = pj < 0 ? 0 : (pj > Lc - 1 ? Lc - 1 : pj);
        oc[k] = labels[cj];
        int cjm = cj > 0 ? cj - 1 : 0;
        float sk = (pj >= 1 && labels[cj] != labels[cjm]) ? 1.f : 0.f;
        SK[k] = make_float2(0.f, sk);
    }

    int Tb = input_len[b]; if (Tb > Tc) Tb = Tc;
    const int smax = 2 * label_len[b];
    const float* base = y_pred + (size_t)b * Tc * Cc;

    // BFP init: pair 0 alive with E=0, others dead.
    float2 A = make_float2(0.f, 0.f);
    int    E = EDEAD;
    if (i == 0) {
        A = make_float2(base[Cc - 1] + EPSV, base[oc[3]] + EPSV);
        E = 0;
    }

    // Preload both prob buffers: PA rows 1..4, PB rows 5..8 (Tb >= 500).
    PS PA, PB;
    loadPS(PA, base + Cc, oc);
    loadPS(PB, base + 5 * Cc, oc);

    int it = 0;
    int t = 1;

    // Main loop: two 4-step chunks per pass (8 steps), alternating buffers.
    for (; t + 7 < Tb; t += 8, it += 2) {
        iter4(A, E, PA, t + 8,  it & 1,       base, Tb, oc, SK, mbuf, ebuf, i);
        iter4(A, E, PB, t + 12, (it + 1) & 1, base, Tb, oc, SK, mbuf, ebuf, i);
    }

    // Possibly one more 4-step chunk (PA holds rows t..t+3 if t+3 < Tb).
    if (t + 3 < Tb) {
        iter4(A, E, PA, t + 8, it & 1, base, Tb, oc, SK, mbuf, ebuf, i);
        t += 4; ++it;
    }

    // Tail: 0..3 single steps (same BFP protocol, 1-pair window).
    for (; t < Tb; ++t, ++it) {
        float2* mb = mbuf[it & 1];
        int*    eb = ebuf[it & 1];
        mb[PADP + i] = A;
        eb[PADP + i] = E;
        __syncthreads();
        float2 N = mb[PADP + i - 1];
        int   En = eb[PADP + i - 1];
        int   Em = E > En ? E : En;
        float fo = exp2i(E - Em), fn = exp2i(En - Em);
        float2 Vo = mul2(A, make_float2(fo, fo));
        float2 Vn = mul2(N, make_float2(fn, fn));
        float pbv = base[(size_t)t * Cc + (Cc - 1)] + EPSV;
        float pov = base[(size_t)t * Cc + oc[3]]    + EPSV;
        A = upd(Vo, Vn, SK[3], make_float2(pbv, pov));
        float m = fmaxf(A.x, A.y);
        int e = ((__float_as_int(m) >> 23) & 255) - 127;
        float sfac = exp2i(-e);
        A = mul2(A, make_float2(sfac, sfac));
        E = Em + e;
    }

    // Final readout: positions smax (pair smax/2, lo) and smax-1
    // (pair smax/2-1, hi). smax is even and >= 100.
    float2* mb = mbuf[it & 1];
    int*    eb = ebuf[it & 1];
    mb[PADP + i] = A;
    eb[PADP + i] = E;
    __syncthreads();
    if (i == 0) {
        int   jL = smax >> 1;
        float mL = mb[PADP + jL].x;     int EL = eb[PADP + jL];
        float mP = mb[PADP + jL - 1].y; int EP = eb[PADP + jL - 1];
        int Em = EL > EP ? EL : EP;
        float r = mL * exp2i(EL - Em) + mP * exp2i(EP - Em);
        out[b] = -LN2F * (lg2a(r) + (float)Em);
    }
}

extern "C" void kernel_launch(void* const* d_in, const int* in_sizes, int n_in,
                              void* d_out, int out_size)
{
    const int*   y_true    = (const int*)  d_in[0];  // [B,L] int32
    const float* y_pred    = (const float*)d_in[1];  // [B,T,C] float32
    const int*   input_len = (const int*)  d_in[2];  // [B] int32
    const int*   label_len = (const int*)  d_in[3];  // [B] int32
    float*       out       = (float*)d_out;          // [B,1] float32

    ctc_loss_kernel<<<Bc, NTHREADS>>>(y_true, y_pred, input_len, label_len, out);
}

// round 17
// speedup vs baseline: 1.3806x; 1.0208x over previous
#include <cuda_runtime.h>
#include <math.h>

// CTC loss forward+backward split. B=64,T=1000,C=128(blank=127),L=100,S=201.
// One CTA per batch element, 256 threads = 2 groups of 128 on named barriers:
//   group 0: forward alpha, steps 1..Tm-1
//   group 1: backward beta, rows Tb-1..Tm      (Tm=(Tb+1)/2)
// loss = -log( sum_s alpha_{Tm-1}(s) * beta_{Tm-1}(s) ), serial depth halved.
// Each group: 2 positions/thread in f32x2, block-floating-point (linear
// mantissa + int exponent), 4-step fused pyramid, depth-2 prob prefetch,
// zero MUFU in the loop.

#define Bc 64
#define Tc 1000
#define Cc 128
#define Lc 100
#define NTHREADS 256
#define GT 128
#define NPAIR 128
#define PADP 4
#define BUFN (PADP + NPAIR + PADP)
#define EDEAD (-(1 << 29))

#define EPSV (1e-7f)
#define LN2F 0.6931471805599453f

__device__ __forceinline__ float lg2a(float x) {
    float y; asm("lg2.approx.f32 %0, %1;" : "=f"(y) : "f"(x)); return y;
}
__device__ __forceinline__ float2 add2(float2 a, float2 b) {
    float2 r;
    asm("{\n\t.reg .b64 A,B,D;\n\t"
        "mov.b64 A,{%2,%3};\n\tmov.b64 B,{%4,%5};\n\t"
        "add.rn.f32x2 D,A,B;\n\t"
        "mov.b64 {%0,%1},D;\n\t}"
        : "=f"(r.x), "=f"(r.y)
        : "f"(a.x), "f"(a.y), "f"(b.x), "f"(b.y));
    return r;
}
__device__ __forceinline__ float2 mul2(float2 a, float2 b) {
    float2 r;
    asm("{\n\t.reg .b64 A,B,D;\n\t"
        "mov.b64 A,{%2,%3};\n\tmov.b64 B,{%4,%5};\n\t"
        "mul.rn.f32x2 D,A,B;\n\t"
        "mov.b64 {%0,%1},D;\n\t}"
        : "=f"(r.x), "=f"(r.y)
        : "f"(a.x), "f"(a.y), "f"(b.x), "f"(b.y));
    return r;
}
__device__ __forceinline__ float2 fma2(float2 a, float2 b, float2 c) {
    float2 r;
    asm("{\n\t.reg .b64 A,B,C,D;\n\t"
        "mov.b64 A,{%2,%3};\n\tmov.b64 B,{%4,%5};\n\tmov.b64 C,{%6,%7};\n\t"
        "fma.rn.f32x2 D,A,B,C;\n\t"
        "mov.b64 {%0,%1},D;\n\t}"
        : "=f"(r.x), "=f"(r.y)
        : "f"(a.x), "f"(a.y), "f"(b.x), "f"(b.y), "f"(c.x), "f"(c.y));
    return r;
}
__device__ __forceinline__ float exp2i(int d) {
    int e = 127 + d; e = e < 0 ? 0 : e;
    return __int_as_float(e << 23);
}
__device__ __forceinline__ void gbar(int barid) {
    asm volatile("bar.sync %0, %1;" :: "r"(barid), "n"(GT) : "memory");
}
// Forward step for pair j: lo=(v2j+v2j-1)*pb; hi=(v2j+1+v2j+sk*v2j-1)*po
__device__ __forceinline__ float2 upd(float2 Q, float2 Qm1, float2 SK, float2 P) {
    float2 S1 = make_float2(Qm1.y, Q.x);
    return mul2(fma2(SK, Qm1, add2(Q, S1)), P);
}
// Backward combine: v_new = {U.x+U.y, U.y+U1.x+skb*U1.y}
__device__ __forceinline__ float2 bcomb(float2 U, float2 U1, float2 SKB) {
    float2 T = make_float2(U.y, U1.x);
    return fma2(SKB, U1, add2(U, T));
}

// ---------- forward prob set (13 scalars, rows R..R+3) ----------
struct PS {
    float bl[4];
    float o0, o1[2], o2[3], o3[4];
};
__device__ __forceinline__ void loadPS(PS& P, const float* R, const int* oc) {
    P.bl[0] = R[Cc - 1];          P.bl[1] = R[Cc + Cc - 1];
    P.bl[2] = R[2 * Cc + Cc - 1]; P.bl[3] = R[3 * Cc + Cc - 1];
    P.o0    = R[oc[0]];
    P.o1[0] = R[oc[1]];      P.o1[1] = R[Cc + oc[1]];
    P.o2[0] = R[oc[2]];      P.o2[1] = R[Cc + oc[2]]; P.o2[2] = R[2 * Cc + oc[2]];
    P.o3[0] = R[oc[3]];      P.o3[1] = R[Cc + oc[3]];
    P.o3[2] = R[2 * Cc + oc[3]]; P.o3[3] = R[3 * Cc + oc[3]];
}

__device__ __forceinline__ void iter4f(
    float2& A, int& E, PS& P, int tpre, int itp,
    const float* base, int Tlim, const int* oc, const float2* SK,
    float2* mb2, int* eb2, int i, int barid)
{
    float b0 = P.bl[0] + EPSV, b1 = P.bl[1] + EPSV;
    float b2 = P.bl[2] + EPSV, b3 = P.bl[3] + EPSV;
    float2 P1[4] = { make_float2(b0, P.o0    + EPSV),
                     make_float2(b0, P.o1[0] + EPSV),
                     make_float2(b0, P.o2[0] + EPSV),
                     make_float2(b0, P.o3[0] + EPSV) };
    float2 P2[3] = { make_float2(b1, P.o1[1] + EPSV),
                     make_float2(b1, P.o2[1] + EPSV),
                     make_float2(b1, P.o3[1] + EPSV) };
    float2 P3[2] = { make_float2(b2, P.o2[2] + EPSV),
                     make_float2(b2, P.o3[2] + EPSV) };
    float2 P4    =   make_float2(b3, P.o3[3] + EPSV);

    float2* mb = mb2 + itp * BUFN;
    int*    eb = eb2 + itp * BUFN;
    mb[PADP + i] = A;
    eb[PADP + i] = E;
    gbar(barid);

    { int r0 = tpre; if (r0 > Tlim - 4) r0 = Tlim - 4;
      loadPS(P, base + (size_t)r0 * Cc, oc); }

    float2 W[4]; int Ew[4];
    #pragma unroll
    for (int j = 0; j < 4; ++j) { W[j] = mb[i + j]; Ew[j] = eb[i + j]; }

    int Em = E;
    #pragma unroll
    for (int j = 0; j < 4; ++j) Em = Ew[j] > Em ? Ew[j] : Em;

    float2 V[5];
    #pragma unroll
    for (int j = 0; j < 4; ++j) {
        float f = exp2i(Ew[j] - Em);
        V[j] = mul2(W[j], make_float2(f, f));
    }
    { float f = exp2i(E - Em); V[4] = mul2(A, make_float2(f, f)); }

    float2 L1[4];
    #pragma unroll
    for (int k = 0; k < 4; ++k) L1[k] = upd(V[k + 1], V[k], SK[k], P1[k]);
    float2 L2[3];
    #pragma unroll
    for (int k = 0; k < 3; ++k) L2[k] = upd(L1[k + 1], L1[k], SK[k + 1], P2[k]);
    float2 L3[2];
    #pragma unroll
    for (int k = 0; k < 2; ++k) L3[k] = upd(L2[k + 1], L2[k], SK[k + 2], P3[k]);
    A = upd(L3[1], L3[0], SK[3], P4);

    float m = fmaxf(A.x, A.y);
    int e = ((__float_as_int(m) >> 23) & 255) - 127;
    float sfac = exp2i(-e);
    A = mul2(A, make_float2(sfac, sfac));
    E = Em + e;
}

// ---------- backward prob set (18 scalars, rows R..R-3) ----------
struct PSB {
    float bl[4];
    float q0[4], q1[4], q2[3], q3[2], q4;
};
__device__ __forceinline__ void loadPSB(PSB& P, const float* R, const int* ocb) {
    P.bl[0] = R[Cc - 1];            P.bl[1] = R[-Cc + Cc - 1];
    P.bl[2] = R[-2 * Cc + Cc - 1];  P.bl[3] = R[-3 * Cc + Cc - 1];
    P.q0[0] = R[ocb[0]]; P.q0[1] = R[-Cc + ocb[0]];
    P.q0[2] = R[-2 * Cc + ocb[0]]; P.q0[3] = R[-3 * Cc + ocb[0]];
    P.q1[0] = R[ocb[1]]; P.q1[1] = R[-Cc + ocb[1]];
    P.q1[2] = R[-2 * Cc + ocb[1]]; P.q1[3] = R[-3 * Cc + ocb[1]];
    P.q2[0] = R[ocb[2]]; P.q2[1] = R[-Cc + ocb[2]]; P.q2[2] = R[-2 * Cc + ocb[2]];
    P.q3[0] = R[ocb[3]]; P.q3[1] = R[-Cc + ocb[3]];
    P.q4    = R[ocb[4]];
}

__device__ __forceinline__ void iter4b(
    float2& A, int& E, PSB& P, int tpre, int itp,
    const float* base, int Tm, const int* ocb, const float2* SKB,
    float2* mb2, int* eb2, int i, int barid)
{
    float bl0 = P.bl[0] + EPSV, bl1 = P.bl[1] + EPSV;
    float bl2 = P.bl[2] + EPSV, bl3 = P.bl[3] + EPSV;
    float a00 = P.q0[0] + EPSV, a01 = P.q0[1] + EPSV, a02 = P.q0[2] + EPSV, a03 = P.q0[3] + EPSV;
    float a10 = P.q1[0] + EPSV, a11 = P.q1[1] + EPSV, a12 = P.q1[2] + EPSV, a13 = P.q1[3] + EPSV;
    float a20 = P.q2[0] + EPSV, a21 = P.q2[1] + EPSV, a22 = P.q2[2] + EPSV;
    float a30 = P.q3[0] + EPSV, a31 = P.q3[1] + EPSV;
    float a4  = P.q4    + EPSV;

    float2* mb = mb2 + itp * BUFN;
    int*    eb = eb2 + itp * BUFN;
    mb[PADP + i] = A;
    eb[PADP + i] = E;
    gbar(barid);

    { int r0 = tpre; if (r0 < Tm + 3) r0 = Tm + 3;
      loadPSB(P, base + (size_t)r0 * Cc, ocb); }

    float2 W[4]; int Ew[4];
    #pragma unroll
    for (int j = 0; j < 4; ++j) { W[j] = mb[PADP + i + 1 + j]; Ew[j] = eb[PADP + i + 1 + j]; }

    int Em = E;
    #pragma unroll
    for (int j = 0; j < 4; ++j) Em = Ew[j] > Em ? Ew[j] : Em;

    float2 v[5];
    { float f = exp2i(E - Em); v[0] = mul2(A, make_float2(f, f)); }
    #pragma unroll
    for (int j = 0; j < 4; ++j) {
        float f = exp2i(Ew[j] - Em);
        v[1 + j] = mul2(W[j], make_float2(f, f));
    }

    float2 U[5];
    // layer 0, row tau (len 5)
    U[0] = mul2(v[0], make_float2(bl0, a00));
    U[1] = mul2(v[1], make_float2(bl0, a10));
    U[2] = mul2(v[2], make_float2(bl0, a20));
    U[3] = mul2(v[3], make_float2(bl0, a30));
    U[4] = mul2(v[4], make_float2(bl0, a4));
    v[0] = bcomb(U[0], U[1], SKB[0]);
    v[1] = bcomb(U[1], U[2], SKB[1]);
    v[2] = bcomb(U[2], U[3], SKB[2]);
    v[3] = bcomb(U[3], U[4], SKB[3]);
    // layer 1, row tau-1 (len 4)
    U[0] = mul2(v[0], make_float2(bl1, a01));
    U[1] = mul2(v[1], make_float2(bl1, a11));
    U[2] = mul2(v[2], make_float2(bl1, a21));
    U[3] = mul2(v[3], make_float2(bl1, a31));
    v[0] = bcomb(U[0], U[1], SKB[0]);
    v[1] = bcomb(U[1], U[2], SKB[1]);
    v[2] = bcomb(U[2], U[3], SKB[2]);
    // layer 2, row tau-2 (len 3)
    U[0] = mul2(v[0], make_float2(bl2, a02));
    U[1] = mul2(v[1], make_float2(bl2, a12));
    U[2] = mul2(v[2], make_float2(bl2, a22));
    v[0] = bcomb(U[0], U[1], SKB[0]);
    v[1] = bcomb(U[1], U[2], SKB[1]);
    // layer 3, row tau-3 (len 2)
    U[0] = mul2(v[0], make_float2(bl3, a03));
    U[1] = mul2(v[1], make_float2(bl3, a13));
    A = bcomb(U[0], U[1], SKB[0]);

    float m = fmaxf(A.x, A.y);
    int e = ((__float_as_int(m) >> 23) & 255) - 127;
    float sfac = exp2i(-e);
    A = mul2(A, make_float2(sfac, sfac));
    E = Em + e;
}

__global__ __launch_bounds__(NTHREADS, 1)
void ctc_loss_kernel(const int* __restrict__ y_true,
                     const float* __restrict__ y_pred,
                     const int* __restrict__ input_len,
                     const int* __restrict__ label_len,
                     float* __restrict__ out)
{
    const int tid = threadIdx.x;
    const int g   = tid >> 7;          // 0 = forward, 1 = backward
    const int i   = tid & (GT - 1);    // pair index
    const int b   = blockIdx.x;
    const int barid = g + 1;

    __shared__ float2 mbuf[2][2 * BUFN];
    __shared__ int    ebuf[2][2 * BUFN];
    __shared__ int    labels[Lc];
    __shared__ float2 fmA[NPAIR], fmB[NPAIR];
    __shared__ int    feA[NPAIR], feB[NPAIR];

    if (g == 0 && i < Lc) labels[i] = y_true[b * Lc + i];
    // dead-init both parity buffers' front and back pads for this group
    if (i < PADP) {
        #pragma unroll
        for (int p = 0; p < 2; ++p) {
            mbuf[g][p * BUFN + i] = make_float2(0.f, 0.f);
            ebuf[g][p * BUFN + i] = EDEAD;
            mbuf[g][p * BUFN + PADP + NPAIR + i] = make_float2(0.f, 0.f);
            ebuf[g][p * BUFN + PADP + NPAIR + i] = EDEAD;
        }
    }
    __syncthreads();

    int Tb = input_len[b]; if (Tb > Tc) Tb = Tc;
    const int smax = 2 * label_len[b];
    const int Tm   = (Tb + 1) >> 1;
    const float* base = y_pred + (size_t)b * Tc * Cc;

    float2* mb2 = mbuf[g];
    int*    eb2 = ebuf[g];

    if (g == 0) {
        // ---------------- FORWARD: alpha over steps 1..Tm-1 ----------------
        int    oc[4];
        float2 SK[4];
        #pragma unroll
        for (int k = 0; k < 4; ++k) {
            int pj = i - 3 + k;
            int cj = pj < 0 ? 0 : (pj > Lc - 1 ? Lc - 1 : pj);
            oc[k] = labels[cj];
            int cjm = cj > 0 ? cj - 1 : 0;
            float sk = (pj >= 1 && labels[cj] != labels[cjm]) ? 1.f : 0.f;
            SK[k] = make_float2(0.f, sk);
        }

        float2 A = make_float2(0.f, 0.f);
        int    E = EDEAD;
        if (i == 0) {
            A = make_float2(base[Cc - 1] + EPSV, base[oc[3]] + EPSV);
            E = 0;
        }

        PS PA, PB;
        loadPS(PA, base + Cc, oc);
        loadPS(PB, base + 5 * Cc, oc);

        int it = 0, t = 1;
        for (; t + 7 < Tm; t += 8, it += 2) {
            iter4f(A, E, PA, t + 8,  it & 1,       base, Tm, oc, SK, mb2, eb2, i, barid);
            iter4f(A, E, PB, t + 12, (it + 1) & 1, base, Tm, oc, SK, mb2, eb2, i, barid);
        }
        if (t + 3 < Tm) {
            iter4f(A, E, PA, t + 8, it & 1, base, Tm, oc, SK, mb2, eb2, i, barid);
            t += 4; ++it;
        }
        for (; t < Tm; ++t, ++it) {
            float2* mb = mb2 + (it & 1) * BUFN;
            int*    eb = eb2 + (it & 1) * BUFN;
            mb[PADP + i] = A;
            eb[PADP + i] = E;
            gbar(barid);
            float2 N = mb[PADP + i - 1];
            int   En = eb[PADP + i - 1];
            int   Em = E > En ? E : En;
            float fo = exp2i(E - Em), fn = exp2i(En - Em);
            float2 Vo = mul2(A, make_float2(fo, fo));
            float2 Vn = mul2(N, make_float2(fn, fn));
            float pbv = base[(size_t)t * Cc + (Cc - 1)] + EPSV;
            float pov = base[(size_t)t * Cc + oc[3]]    + EPSV;
            A = upd(Vo, Vn, SK[3], make_float2(pbv, pov));
            float m = fmaxf(A.x, A.y);
            int e = ((__float_as_int(m) >> 23) & 255) - 127;
            float sfac = exp2i(-e);
            A = mul2(A, make_float2(sfac, sfac));
            E = Em + e;
        }
        fmA[i] = A; feA[i] = E;
    } else {
        // ---------------- BACKWARD: beta over rows Tb-1..Tm ----------------
        int    ocb[5];
        float2 SKB[4];
        #pragma unroll
        for (int k = 0; k < 5; ++k) {
            int cj = i + k; if (cj > Lc - 1) cj = Lc - 1;
            ocb[k] = labels[cj];
        }
        #pragma unroll
        for (int k = 0; k < 4; ++k) {
            int cj = i + k + 1; if (cj > Lc - 1) cj = Lc - 1;
            float sk = (labels[cj] != labels[cj - 1]) ? 1.f : 0.f;
            SKB[k] = make_float2(0.f, sk);
        }

        // beta init at t = Tb-1: 1 at positions smax, smax-1.
        float2 A = make_float2(0.f, 0.f);
        int    E = EDEAD;
        int jL = smax >> 1;
        if (i == jL)     { A = make_float2(1.f, 0.f); E = 0; }
        if (i == jL - 1) { A = make_float2(0.f, 1.f); E = 0; }

        PSB PA, PB;
        int tau = Tb - 1;
        loadPSB(PA, base + (size_t)tau * Cc, ocb);
        loadPSB(PB, base + (size_t)(tau - 4) * Cc, ocb);

        int it = 0;
        for (; tau - 7 >= Tm; tau -= 8, it += 2) {
            iter4b(A, E, PA, tau - 8,  it & 1,       base, Tm, ocb, SKB, mb2, eb2, i, barid);
            iter4b(A, E, PB, tau - 12, (it + 1) & 1, base, Tm, ocb, SKB, mb2, eb2, i, barid);
        }
        if (tau - 3 >= Tm) {
            iter4b(A, E, PA, tau - 8, it & 1, base, Tm, ocb, SKB, mb2, eb2, i, barid);
            tau -= 4; ++it;
        }
        for (; tau >= Tm; --tau, ++it) {
            float2* mb = mb2 + (it & 1) * BUFN;
            int*    eb = eb2 + (it & 1) * BUFN;
            mb[PADP + i] = A;
            eb[PADP + i] = E;
            gbar(barid);
            float2 N = mb[PADP + i + 1];
            int   En = eb[PADP + i + 1];
            int   Em = E > En ? E : En;
            float fo = exp2i(E - Em), fn = exp2i(En - Em);
            float2 Vo = mul2(A, make_float2(fo, fo));
            float2 Vn = mul2(N, make_float2(fn, fn));
            float pbv = base[(size_t)tau * Cc + (Cc - 1)] + EPSV;
            float p0  = base[(size_t)tau * Cc + ocb[0]]   + EPSV;
            float p1  = base[(size_t)tau * Cc + ocb[1]]   + EPSV;
            float2 U0 = mul2(Vo, make_float2(pbv, p0));
            float2 U1 = mul2(Vn, make_float2(pbv, p1));
            A = bcomb(U0, U1, SKB[0]);
            float m = fmaxf(A.x, A.y);
            int e = ((__float_as_int(m) >> 23) & 255) - 127;
            float sfac = exp2i(-e);
            A = mul2(A, make_float2(sfac, sfac));
            E = Em + e;
        }
        fmB[i] = A; feB[i] = E;
    }

    __syncthreads();

    // Combine: total = sum_j (Am_j . Bm_j) * 2^(Ea_j + Eb_j)
    if (tid == 0) {
        int emax = -(1 << 30);
        #pragma unroll 4
        for (int j = 0; j < NPAIR; ++j) {
            int e = feA[j] + feB[j];
            emax = e > emax ? e : emax;
        }
        float sum = 0.f;
        #pragma unroll 4
        for (int j = 0; j < NPAIR; ++j) {
            float dot = fmA[j].x * fmB[j].x + fmA[j].y * fmB[j].y;
            sum += dot * exp2i(feA[j] + feB[j] - emax);
        }
        out[b] = -LN2F * (lg2a(sum) + (float)emax);
    }
}

extern "C" void kernel_launch(void* const* d_in, const int* in_sizes, int n_in,
                              void* d_out, int out_size)
{
    const int*   y_true    = (const int*)  d_in[0];  // [B,L] int32
    const float* y_pred    = (const float*)d_in[1];  // [B,T,C] float32
    const int*   input_len = (const int*)  d_in[2];  // [B] int32
    const int*   label_len = (const int*)  d_in[3];  // [B] int32
    float*       out       = (float*)d_out;          // [B,1] float32

    ctc_loss_kernel<<<Bc, NTHREADS>>>(y_true, y_pred, input_len, label_len, out);
}